// round 10
// baseline (speedup 1.0000x reference)
#include <cuda_runtime.h>
#include <cuda_bf16.h>
#include <math.h>
#include <stdint.h>

#define N_PTS   8192
#define D_DIM   8
#define K_DIM   64
#define Q_DIM   16
#define KQ      1024
#define TWO_PI  6.283185307179586f

#define EPHI_SZ (N_PTS * KQ)    // 8388608
#define G_SZ    (KQ * KQ)       // 1048576
// d_out layout: [E_phi (N,KQ) | G (KQ,KQ) | E_cos_sq (N,KQ)]

// -------- device scratch --------
__device__ float g_Ew[D_DIM * KQ];
__device__ float g_C [D_DIM * KQ];
__device__ float g_zs[D_DIM * KQ];
__device__ float g_dpart[256 * KQ];
__device__ __nv_bfloat16 g_hi[(size_t)KQ * N_PTS];
__device__ __nv_bfloat16 g_lo[(size_t)KQ * N_PTS];

// ---------------------------------------------------------------------------
// helpers
// ---------------------------------------------------------------------------
__device__ __forceinline__ uint32_t smem_u32(const void* p) {
    uint32_t a;
    asm("{ .reg .u64 t; cvta.to.shared.u64 t, %1; cvt.u32.u64 %0, t; }"
        : "=r"(a) : "l"(p));
    return a;
}
__device__ __forceinline__ void cp16(uint32_t dst, const void* src) {
    asm volatile("cp.async.cg.shared.global [%0], [%1], 16;"
                 :: "r"(dst), "l"(src));
}
__device__ __forceinline__ void cp_commit() {
    asm volatile("cp.async.commit_group;" ::: "memory");
}
template <int N>
__device__ __forceinline__ void cp_wait() {
    asm volatile("cp.async.wait_group %0;" :: "n"(N) : "memory");
}
__device__ __forceinline__ void ldsm4(uint32_t* r, uint32_t addr) {
    asm volatile("ldmatrix.sync.aligned.m8n8.x4.shared.b16 {%0,%1,%2,%3}, [%4];"
                 : "=r"(r[0]), "=r"(r[1]), "=r"(r[2]), "=r"(r[3]) : "r"(addr));
}
__device__ __forceinline__ void mma_bf16(float* c, const uint32_t* a,
                                         uint32_t b0, uint32_t b1) {
    asm volatile(
        "mma.sync.aligned.m16n8k16.row.col.f32.bf16.bf16.f32 "
        "{%0,%1,%2,%3}, {%4,%5,%6,%7}, {%8,%9}, {%0,%1,%2,%3};"
        : "+f"(c[0]), "+f"(c[1]), "+f"(c[2]), "+f"(c[3])
        : "r"(a[0]), "r"(a[1]), "r"(a[2]), "r"(a[3]), "r"(b0), "r"(b1));
}

// swizzled offset within a 64B-row warp-private buffer (16B granules)
__device__ __forceinline__ uint32_t swz(int row, int seg) {
    return (uint32_t)(row * 64 + ((seg ^ ((row >> 1) & 3)) << 4));
}

// ---------------------------------------------------------------------------
// Kernel 0: precompute coefficient tables
// ---------------------------------------------------------------------------
__global__ void precompute_kernel(const float* __restrict__ z,
                                  const float* __restrict__ mu,
                                  const float* __restrict__ stdv,
                                  const float* __restrict__ var_mu_w,
                                  const float* __restrict__ var_sigma_w)
{
    int idx = blockIdx.x * blockDim.x + threadIdx.x;
    if (idx >= D_DIM * KQ) return;
    int d  = idx >> 10;
    int kq = idx & (KQ - 1);
    int q  = kq & (Q_DIM - 1);

    float mean_p = 1.0f / (mu[d * Q_DIM + q] + 1e-8f);
    float std_p  = 1.0f / (TWO_PI * stdv[d * Q_DIM + q] + 1e-8f);

    g_Ew[idx] = mean_p + std_p * var_mu_w[idx];
    g_C [idx] = std_p * std_p * var_sigma_w[idx];
    g_zs[idx] = TWO_PI * z[idx];
}

// ---------------------------------------------------------------------------
// Kernel 1: fused E_phi, E_cos_sq, split-bf16 transposed hi/lo, diag partials
// ---------------------------------------------------------------------------
__global__ void __launch_bounds__(256) ephi_kernel(const float* __restrict__ X,
                            const float* __restrict__ weight,
                            const float* __restrict__ alpha,
                            float* __restrict__ out)
{
    const int tid = threadIdx.x;
    const int kq0 = blockIdx.x * 256;
    const int kq  = kq0 + tid;
    const int n0  = blockIdx.y * 32;

    __shared__ float Xs[256];
    __shared__ __nv_bfloat16 s_hi[256][34];
    __shared__ __nv_bfloat16 s_lo[256][34];

    Xs[tid] = TWO_PI * X[n0 * D_DIM + tid];
    __syncthreads();

    float ew[D_DIM], cc[D_DIM], zz[D_DIM];
#pragma unroll
    for (int d = 0; d < D_DIM; ++d) {
        ew[d] = g_Ew[d * KQ + kq];
        cc[d] = g_C [d * KQ + kq];
        zz[d] = g_zs[d * KQ + kq];
    }
    const int   q    = kq & (Q_DIM - 1);
    const float a    = alpha[kq];
    const float coef = 2.0f * weight[q] * (1.0f / (float)K_DIM);
    const float sq   = sqrtf(coef);

    float* __restrict__ outE = out;
    float* __restrict__ outC = out + EPHI_SZ + G_SZ;

    float dsum = 0.0f;
#pragma unroll 4
    for (int r = 0; r < 32; ++r) {
        float phase = 0.0f, s = 0.0f;
#pragma unroll
        for (int d = 0; d < D_DIM; ++d) {
            float xb = Xs[r * D_DIM + d] - zz[d];
            phase = fmaf(xb, ew[d], phase);
            s     = fmaf(cc[d], xb * xb, s);
        }
        float cw    = __cosf(a + phase);
        float decay = __expf(-0.5f * s);

        const int n = n0 + r;
        float E = sq * decay * cw;
        outE[n * KQ + kq] = E;

        float d2  = decay * decay;
        float d4  = d2 * d2;
        float c2w = 2.0f * cw * cw - 1.0f;
        float ecs = coef * (0.5f + 0.5f * d4 * c2w);
        outC[n * KQ + kq] = ecs;
        dsum += ecs;

        __nv_bfloat16 h = __float2bfloat16(E);
        s_hi[tid][r] = h;
        s_lo[tid][r] = __float2bfloat16(E - __bfloat162float(h));
    }
    g_dpart[blockIdx.y * KQ + kq] = dsum;
    __syncthreads();

    uint32_t* __restrict__ H = (uint32_t*)g_hi;
    uint32_t* __restrict__ L = (uint32_t*)g_lo;
#pragma unroll
    for (int i = 0; i < 16; ++i) {
        int v   = tid + i * 256;
        int row = v >> 4;
        int seg = v & 15;
        uint32_t h2 = *(const uint32_t*)&s_hi[row][seg * 2];
        uint32_t l2 = *(const uint32_t*)&s_lo[row][seg * 2];
        size_t o = ((size_t)(kq0 + row) * N_PTS + n0) / 2 + seg;
        H[o] = h2;
        L[o] = l2;
    }
}

// ---------------------------------------------------------------------------
// Kernel 2: SYRK, warp-autonomous pipelines (NO mainloop __syncthreads).
// 136 upper-triangular 64x64 tiles, 256 threads = 8 warps.
// Warp (ms, kset): ms = m-half (32 rows), kset = k-quarter (32 of 128 per sc).
// Warp-private smem: stage = AHI 2KB | ALO 2KB | BHI 4KB | BLO 4KB = 12KB,
// double buffered -> 24KB/warp, 192KB/CTA. 64B rows, seg^((row>>1)&3) swizzle.
// Mainloop structure identical to R8 (proven); refill is issue-split into
// A-part / B-part around the hl chain, single commit (same group accounting).
// Epilogue: 4-set smem reduce + write/mirror; diagonal tiles reduce g_dpart.
// ---------------------------------------------------------------------------
#define A_HI_OFF 0
#define A_LO_OFF 2048
#define B_HI_OFF 4096
#define B_LO_OFF 8192
#define WSTAGE   12288
#define WBUF     (2 * WSTAGE)        // 24576 per warp
#define SMEM_SYRK (8 * WBUF)         // 196608
#define NSC 64
#define RED_STRIDE 65
#define RED_BYTES (64 * RED_STRIDE * 4)   // 16640
#define SDIAG_OFF (3 * RED_BYTES)         // 49920

// A refill: 32 rows x 32k, hi+lo = 256 16B-chunks (8 cp per lane)
__device__ __forceinline__ void load_warp_A(uint32_t stage_base, int i0r,
                                            size_t koff, int lane)
{
#pragma unroll
    for (int it = 0; it < 8; ++it) {
        int cid = it * 32 + lane;
        int h   = cid >> 7;
        int rc  = cid & 127;
        int row = rc >> 2;
        int seg = rc & 3;
        uint32_t dst = stage_base + (uint32_t)(h ? A_LO_OFF : A_HI_OFF) + swz(row, seg);
        const __nv_bfloat16* base = h ? g_lo : g_hi;
        cp16(dst, (const char*)(base + (size_t)(i0r + row) * N_PTS + koff) + seg * 16);
    }
}
// B refill: 64 rows x 32k, hi+lo = 512 16B-chunks (16 cp per lane)
__device__ __forceinline__ void load_warp_B(uint32_t stage_base, int j0,
                                            size_t koff, int lane)
{
#pragma unroll
    for (int it = 0; it < 16; ++it) {
        int cid = it * 32 + lane;
        int h   = cid >> 8;
        int rc  = cid & 255;
        int row = rc >> 2;
        int seg = rc & 3;
        uint32_t dst = stage_base + (uint32_t)(h ? B_LO_OFF : B_HI_OFF) + swz(row, seg);
        const __nv_bfloat16* base = h ? g_lo : g_hi;
        cp16(dst, (const char*)(base + (size_t)(j0 + row) * N_PTS + koff) + seg * 16);
    }
}

__global__ void __launch_bounds__(256, 1) syrk_mma_kernel(float* __restrict__ out)
{
    extern __shared__ __align__(1024) char smem[];
    const uint32_t sbase = smem_u32(smem);
    const int tid  = threadIdx.x;
    const int lane = tid & 31;
    const int wid  = tid >> 5;
    const int ms   = wid & 1;               // m-half
    const int kset = wid >> 1;              // k-quarter
    const int wm   = ms * 32;
    const uint32_t wbase = sbase + (uint32_t)wid * WBUF;

    int b = blockIdx.x, ti = 0, rem = b;
    while (rem >= 16 - ti) { rem -= 16 - ti; ++ti; }
    const int tj = ti + rem;
    const int i0 = ti * 64;
    const int j0 = tj * 64;
    const int i0r = i0 + wm;

    // ldmatrix addresses within the private buffer
    const int g  = lane >> 3;
    const int rr = lane & 7;
    uint32_t a_addr[2][2], b_addr[4][2];
#pragma unroll
    for (int mf = 0; mf < 2; ++mf)
#pragma unroll
        for (int ks = 0; ks < 2; ++ks) {
            int m   = mf * 16 + rr + (g & 1) * 8;
            int seg = (g >> 1) + ks * 2;
            a_addr[mf][ks] = wbase + A_HI_OFF + swz(m, seg);
        }
#pragma unroll
    for (int nf2 = 0; nf2 < 4; ++nf2)
#pragma unroll
        for (int ks = 0; ks < 2; ++ks) {
            int n   = nf2 * 16 + rr + (g >> 1) * 8;
            int seg = (g & 1) + ks * 2;
            b_addr[nf2][ks] = wbase + B_HI_OFF + swz(n, seg);
        }

    float acc[2][8][4];
#pragma unroll
    for (int mf = 0; mf < 2; ++mf)
#pragma unroll
        for (int nf = 0; nf < 8; ++nf)
#pragma unroll
            for (int r2 = 0; r2 < 4; ++r2) acc[mf][nf][r2] = 0.0f;

    const size_t kbase = (size_t)kset * 32;
    load_warp_A(wbase, i0r, kbase, lane);
    load_warp_B(wbase, j0,  kbase, lane);
    cp_commit();
    load_warp_A(wbase + WSTAGE, i0r, kbase + 128, lane);
    load_warp_B(wbase + WSTAGE, j0,  kbase + 128, lane);
    cp_commit();

    for (int sc = 0; sc < NSC; ++sc) {
        cp_wait<1>();                         // this warp's chunk sc complete
        const uint32_t so = (uint32_t)(sc & 1) * WSTAGE;
        const size_t knext = kbase + (size_t)(sc + 2) * 128;
        const bool pre = (sc + 2 < NSC);

#pragma unroll
        for (int ks = 0; ks < 2; ++ks) {
            uint32_t ah[2][4], al[2][4], bh[4][4], bl[4][4];
            ldsm4(ah[0], a_addr[0][ks] + so);
            ldsm4(ah[1], a_addr[1][ks] + so);
            ldsm4(al[0], a_addr[0][ks] + so + (A_LO_OFF - A_HI_OFF));
            ldsm4(al[1], a_addr[1][ks] + so + (A_LO_OFF - A_HI_OFF));
#pragma unroll
            for (int nf2 = 0; nf2 < 4; ++nf2) {
                ldsm4(bh[nf2], b_addr[nf2][ks] + so);
                ldsm4(bl[nf2], b_addr[nf2][ks] + so + (B_LO_OFF - B_HI_OFF));
            }

            // hh chain
#pragma unroll
            for (int mf = 0; mf < 2; ++mf)
#pragma unroll
                for (int nf = 0; nf < 8; ++nf)
                    mma_bf16(acc[mf][nf], ah[mf],
                             bh[nf >> 1][(nf & 1) * 2], bh[nf >> 1][(nf & 1) * 2 + 1]);

            // refill part 1 (A): after ALL ldsm of this stage (ks==1 only)
            if (ks == 1 && pre)
                load_warp_A(wbase + so, i0r, knext, lane);

            // hl chain
#pragma unroll
            for (int mf = 0; mf < 2; ++mf)
#pragma unroll
                for (int nf = 0; nf < 8; ++nf)
                    mma_bf16(acc[mf][nf], ah[mf],
                             bl[nf >> 1][(nf & 1) * 2], bl[nf >> 1][(nf & 1) * 2 + 1]);

            // refill part 2 (B) + single commit per iteration (as in R8)
            if (ks == 1) {
                if (pre) load_warp_B(wbase + so, j0, knext, lane);
                cp_commit();
            }

            // lh chain
#pragma unroll
            for (int mf = 0; mf < 2; ++mf)
#pragma unroll
                for (int nf = 0; nf < 8; ++nf)
                    mma_bf16(acc[mf][nf], al[mf],
                             bh[nf >> 1][(nf & 1) * 2], bh[nf >> 1][(nf & 1) * 2 + 1]);
        }
    }

    // ---- epilogue: 4-set reduction + write (tile, mirror, diag) ----
    __syncthreads();                          // all warps done with private bufs
    const int r0   = lane >> 2;
    const int cpos = (lane & 3) * 2;
    const bool diagTile = (ti == tj);
    float (*sdiag)[64] = (float (*)[64])(smem + SDIAG_OFF);

    if (diagTile) {                           // per-column sums of E_cos_sq
        const int c  = tid & 63;
        const int gq = tid >> 6;              // 0..3
        float s = 0.0f;
#pragma unroll 8
        for (int p = gq * 64; p < gq * 64 + 64; ++p)
            s += g_dpart[p * KQ + j0 + c];
        sdiag[gq][c] = s;
    }

    if (kset >= 1) {
        float (*red)[RED_STRIDE] =
            (float (*)[RED_STRIDE])(smem + (size_t)(kset - 1) * RED_BYTES);
#pragma unroll
        for (int mf = 0; mf < 2; ++mf)
#pragma unroll
            for (int nf = 0; nf < 8; ++nf) {
                const int rl = wm + mf * 16 + r0;
                const int cl = nf * 8 + cpos;
                red[rl][cl]         = acc[mf][nf][0];
                red[rl][cl + 1]     = acc[mf][nf][1];
                red[rl + 8][cl]     = acc[mf][nf][2];
                red[rl + 8][cl + 1] = acc[mf][nf][3];
            }
    }
    __syncthreads();

    if (kset == 0) {
        float* __restrict__ G = out + EPHI_SZ;
        float (*red0)[RED_STRIDE] = (float (*)[RED_STRIDE])(smem);
        float (*red1)[RED_STRIDE] = (float (*)[RED_STRIDE])(smem + RED_BYTES);
        float (*red2)[RED_STRIDE] = (float (*)[RED_STRIDE])(smem + 2 * RED_BYTES);
#pragma unroll
        for (int mf = 0; mf < 2; ++mf)
#pragma unroll
            for (int nf = 0; nf < 8; ++nf)
#pragma unroll
                for (int r2 = 0; r2 < 4; ++r2) {
                    const int rl = wm + mf * 16 + r0 + (r2 >> 1) * 8;
                    const int cl = nf * 8 + cpos + (r2 & 1);
                    const int gi = i0 + rl;
                    const int gj = j0 + cl;
                    float val = acc[mf][nf][r2]
                              + red0[rl][cl] + red1[rl][cl] + red2[rl][cl];
                    if (diagTile && gi == gj)
                        val = sdiag[0][cl] + sdiag[1][cl]
                            + sdiag[2][cl] + sdiag[3][cl];
                    G[(size_t)gi * KQ + gj] = val;
                    G[(size_t)gj * KQ + gi] = val;
                }
    }
}

// ---------------------------------------------------------------------------
extern "C" void kernel_launch(void* const* d_in, const int* in_sizes, int n_in,
                              void* d_out, int out_size)
{
    const float* X           = (const float*)d_in[0];
    const float* z           = (const float*)d_in[1];
    const float* weight      = (const float*)d_in[2];
    const float* mu          = (const float*)d_in[3];
    const float* stdv        = (const float*)d_in[4];
    const float* alpha       = (const float*)d_in[5];
    const float* var_mu_w    = (const float*)d_in[6];
    const float* var_sigma_w = (const float*)d_in[7];
    float* out = (float*)d_out;

    cudaFuncSetAttribute(syrk_mma_kernel,
                         cudaFuncAttributeMaxDynamicSharedMemorySize, SMEM_SYRK);

    precompute_kernel<<<32, 256>>>(z, mu, stdv, var_mu_w, var_sigma_w);

    dim3 egrid(KQ / 256, N_PTS / 32);
    ephi_kernel<<<egrid, 256>>>(X, weight, alpha, out);

    syrk_mma_kernel<<<136, 256, SMEM_SYRK>>>(out);
}

// round 11
// speedup vs baseline: 1.0194x; 1.0194x over previous
#include <cuda_runtime.h>
#include <cuda_bf16.h>
#include <math.h>
#include <stdint.h>

#define N_PTS   8192
#define D_DIM   8
#define K_DIM   64
#define Q_DIM   16
#define KQ      1024
#define TWO_PI  6.283185307179586f

#define EPHI_SZ (N_PTS * KQ)    // 8388608
#define G_SZ    (KQ * KQ)       // 1048576
// d_out layout: [E_phi (N,KQ) | G (KQ,KQ) | E_cos_sq (N,KQ)]

// -------- device scratch --------
__device__ float g_dpart[256 * KQ];
__device__ __nv_bfloat16 g_hi[(size_t)KQ * N_PTS];
__device__ __nv_bfloat16 g_lo[(size_t)KQ * N_PTS];

// ---------------------------------------------------------------------------
// helpers
// ---------------------------------------------------------------------------
__device__ __forceinline__ uint32_t smem_u32(const void* p) {
    uint32_t a;
    asm("{ .reg .u64 t; cvta.to.shared.u64 t, %1; cvt.u32.u64 %0, t; }"
        : "=r"(a) : "l"(p));
    return a;
}
__device__ __forceinline__ void cp16(uint32_t dst, const void* src) {
    asm volatile("cp.async.cg.shared.global [%0], [%1], 16;"
                 :: "r"(dst), "l"(src));
}
__device__ __forceinline__ void cp_commit() {
    asm volatile("cp.async.commit_group;" ::: "memory");
}
template <int N>
__device__ __forceinline__ void cp_wait() {
    asm volatile("cp.async.wait_group %0;" :: "n"(N) : "memory");
}
__device__ __forceinline__ void ldsm4(uint32_t* r, uint32_t addr) {
    asm volatile("ldmatrix.sync.aligned.m8n8.x4.shared.b16 {%0,%1,%2,%3}, [%4];"
                 : "=r"(r[0]), "=r"(r[1]), "=r"(r[2]), "=r"(r[3]) : "r"(addr));
}
__device__ __forceinline__ void mma_bf16(float* c, const uint32_t* a,
                                         uint32_t b0, uint32_t b1) {
    asm volatile(
        "mma.sync.aligned.m16n8k16.row.col.f32.bf16.bf16.f32 "
        "{%0,%1,%2,%3}, {%4,%5,%6,%7}, {%8,%9}, {%0,%1,%2,%3};"
        : "+f"(c[0]), "+f"(c[1]), "+f"(c[2]), "+f"(c[3])
        : "r"(a[0]), "r"(a[1]), "r"(a[2]), "r"(a[3]), "r"(b0), "r"(b1));
}

// swizzled offset within a 64B-row warp-private buffer (16B granules)
__device__ __forceinline__ uint32_t swz(int row, int seg) {
    return (uint32_t)(row * 64 + ((seg ^ ((row >> 1) & 3)) << 4));
}

// ---------------------------------------------------------------------------
// Kernel 1: fused E_phi, E_cos_sq, split-bf16 transposed hi/lo, diag partials.
// Coefficient tables computed per-block in smem (replaces precompute kernel).
// ---------------------------------------------------------------------------
__global__ void __launch_bounds__(256) ephi_kernel(const float* __restrict__ X,
                            const float* __restrict__ z,
                            const float* __restrict__ weight,
                            const float* __restrict__ mu,
                            const float* __restrict__ stdv,
                            const float* __restrict__ alpha,
                            const float* __restrict__ var_mu_w,
                            const float* __restrict__ var_sigma_w,
                            float* __restrict__ out)
{
    const int tid = threadIdx.x;
    const int kq0 = blockIdx.x * 256;
    const int kq  = kq0 + tid;
    const int n0  = blockIdx.y * 32;

    __shared__ float Xs[256];
    __shared__ float s_mp[128], s_sp[128];     // mean_p, std_p per (d,q)
    __shared__ __nv_bfloat16 s_hi[256][34];
    __shared__ __nv_bfloat16 s_lo[256][34];

    Xs[tid] = TWO_PI * X[n0 * D_DIM + tid];
    if (tid < 128) {
        s_mp[tid] = 1.0f / (mu[tid] + 1e-8f);
        s_sp[tid] = 1.0f / (TWO_PI * stdv[tid] + 1e-8f);
    }
    __syncthreads();

    const int q = kq & (Q_DIM - 1);
    float ew[D_DIM], cc[D_DIM], zz[D_DIM];
#pragma unroll
    for (int d = 0; d < D_DIM; ++d) {
        const float mp = s_mp[d * Q_DIM + q];
        const float sp = s_sp[d * Q_DIM + q];
        ew[d] = mp + sp * var_mu_w[d * KQ + kq];
        cc[d] = sp * sp * var_sigma_w[d * KQ + kq];
        zz[d] = TWO_PI * z[d * KQ + kq];
    }
    const float a    = alpha[kq];
    const float coef = 2.0f * weight[q] * (1.0f / (float)K_DIM);
    const float sq   = sqrtf(coef);

    float* __restrict__ outE = out;
    float* __restrict__ outC = out + EPHI_SZ + G_SZ;

    float dsum = 0.0f;
#pragma unroll 4
    for (int r = 0; r < 32; ++r) {
        float phase = 0.0f, s = 0.0f;
#pragma unroll
        for (int d = 0; d < D_DIM; ++d) {
            float xb = Xs[r * D_DIM + d] - zz[d];
            phase = fmaf(xb, ew[d], phase);
            s     = fmaf(cc[d], xb * xb, s);
        }
        float cw    = __cosf(a + phase);
        float decay = __expf(-0.5f * s);

        const int n = n0 + r;
        float E = sq * decay * cw;
        outE[n * KQ + kq] = E;

        float d2  = decay * decay;
        float d4  = d2 * d2;
        float c2w = 2.0f * cw * cw - 1.0f;
        float ecs = coef * (0.5f + 0.5f * d4 * c2w);
        outC[n * KQ + kq] = ecs;
        dsum += ecs;

        __nv_bfloat16 h = __float2bfloat16(E);
        s_hi[tid][r] = h;
        s_lo[tid][r] = __float2bfloat16(E - __bfloat162float(h));
    }
    g_dpart[blockIdx.y * KQ + kq] = dsum;
    __syncthreads();

    uint32_t* __restrict__ H = (uint32_t*)g_hi;
    uint32_t* __restrict__ L = (uint32_t*)g_lo;
#pragma unroll
    for (int i = 0; i < 16; ++i) {
        int v   = tid + i * 256;
        int row = v >> 4;
        int seg = v & 15;
        uint32_t h2 = *(const uint32_t*)&s_hi[row][seg * 2];
        uint32_t l2 = *(const uint32_t*)&s_lo[row][seg * 2];
        size_t o = ((size_t)(kq0 + row) * N_PTS + n0) / 2 + seg;
        H[o] = h2;
        L[o] = l2;
    }
}

// ---------------------------------------------------------------------------
// Kernel 2: SYRK, warp-autonomous pipelines (NO mainloop __syncthreads).
// 136 upper-triangular 64x64 tiles, 256 threads = 8 warps.
// Warp (ms, kset): ms = m-half (32 rows), kset = k-quarter (32 of 128 per sc).
// Warp-private smem: stage = AHI 2KB | ALO 2KB | BHI 4KB | BLO 4KB = 12KB,
// double buffered -> 24KB/warp, 192KB/CTA. 64B rows, seg^((row>>1)&3) swizzle.
// Mainloop group accounting identical to R8/R10 (proven): 1 commit/iter,
// cp_wait<1>. ldsm are INTERLEAVED into the mma stream to shrink the
// per-ks serial head (volatile asm order = issue order).
// Epilogue: 4-set smem reduce + write/mirror; diagonal tiles reduce g_dpart.
// ---------------------------------------------------------------------------
#define A_HI_OFF 0
#define A_LO_OFF 2048
#define B_HI_OFF 4096
#define B_LO_OFF 8192
#define WSTAGE   12288
#define WBUF     (2 * WSTAGE)        // 24576 per warp
#define SMEM_SYRK (8 * WBUF)         // 196608
#define NSC 64
#define RED_STRIDE 65
#define RED_BYTES (64 * RED_STRIDE * 4)   // 16640
#define SDIAG_OFF (3 * RED_BYTES)         // 49920

// A refill: 32 rows x 32k, hi+lo = 256 16B-chunks (8 cp per lane)
__device__ __forceinline__ void load_warp_A(uint32_t stage_base, int i0r,
                                            size_t koff, int lane)
{
#pragma unroll
    for (int it = 0; it < 8; ++it) {
        int cid = it * 32 + lane;
        int h   = cid >> 7;
        int rc  = cid & 127;
        int row = rc >> 2;
        int seg = rc & 3;
        uint32_t dst = stage_base + (uint32_t)(h ? A_LO_OFF : A_HI_OFF) + swz(row, seg);
        const __nv_bfloat16* base = h ? g_lo : g_hi;
        cp16(dst, (const char*)(base + (size_t)(i0r + row) * N_PTS + koff) + seg * 16);
    }
}
// B refill: 64 rows x 32k, hi+lo = 512 16B-chunks (16 cp per lane)
__device__ __forceinline__ void load_warp_B(uint32_t stage_base, int j0,
                                            size_t koff, int lane)
{
#pragma unroll
    for (int it = 0; it < 16; ++it) {
        int cid = it * 32 + lane;
        int h   = cid >> 8;
        int rc  = cid & 255;
        int row = rc >> 2;
        int seg = rc & 3;
        uint32_t dst = stage_base + (uint32_t)(h ? B_LO_OFF : B_HI_OFF) + swz(row, seg);
        const __nv_bfloat16* base = h ? g_lo : g_hi;
        cp16(dst, (const char*)(base + (size_t)(j0 + row) * N_PTS + koff) + seg * 16);
    }
}

__global__ void __launch_bounds__(256, 1) syrk_mma_kernel(float* __restrict__ out)
{
    extern __shared__ __align__(1024) char smem[];
    const uint32_t sbase = smem_u32(smem);
    const int tid  = threadIdx.x;
    const int lane = tid & 31;
    const int wid  = tid >> 5;
    const int ms   = wid & 1;               // m-half
    const int kset = wid >> 1;              // k-quarter
    const int wm   = ms * 32;
    const uint32_t wbase = sbase + (uint32_t)wid * WBUF;

    int b = blockIdx.x, ti = 0, rem = b;
    while (rem >= 16 - ti) { rem -= 16 - ti; ++ti; }
    const int tj = ti + rem;
    const int i0 = ti * 64;
    const int j0 = tj * 64;
    const int i0r = i0 + wm;

    // ldmatrix addresses within the private buffer
    const int g  = lane >> 3;
    const int rr = lane & 7;
    uint32_t a_addr[2][2], b_addr[4][2];
#pragma unroll
    for (int mf = 0; mf < 2; ++mf)
#pragma unroll
        for (int ks = 0; ks < 2; ++ks) {
            int m   = mf * 16 + rr + (g & 1) * 8;
            int seg = (g >> 1) + ks * 2;
            a_addr[mf][ks] = wbase + A_HI_OFF + swz(m, seg);
        }
#pragma unroll
    for (int nf2 = 0; nf2 < 4; ++nf2)
#pragma unroll
        for (int ks = 0; ks < 2; ++ks) {
            int n   = nf2 * 16 + rr + (g >> 1) * 8;
            int seg = (g & 1) + ks * 2;
            b_addr[nf2][ks] = wbase + B_HI_OFF + swz(n, seg);
        }

    float acc[2][8][4];
#pragma unroll
    for (int mf = 0; mf < 2; ++mf)
#pragma unroll
        for (int nf = 0; nf < 8; ++nf)
#pragma unroll
            for (int r2 = 0; r2 < 4; ++r2) acc[mf][nf][r2] = 0.0f;

    const size_t kbase = (size_t)kset * 32;
    load_warp_A(wbase, i0r, kbase, lane);
    load_warp_B(wbase, j0,  kbase, lane);
    cp_commit();
    load_warp_A(wbase + WSTAGE, i0r, kbase + 128, lane);
    load_warp_B(wbase + WSTAGE, j0,  kbase + 128, lane);
    cp_commit();

    for (int sc = 0; sc < NSC; ++sc) {
        cp_wait<1>();                         // this warp's chunk sc complete
        const uint32_t so = (uint32_t)(sc & 1) * WSTAGE;
        const size_t knext = kbase + (size_t)(sc + 2) * 128;
        const bool pre = (sc + 2 < NSC);

#pragma unroll
        for (int ks = 0; ks < 2; ++ks) {
            uint32_t ah[2][4], al[2][4], bh[4][4], bl[4][4];
            // minimal head: only the frags the hh(mf0) chain needs
            ldsm4(ah[0], a_addr[0][ks] + so);
            ldsm4(bh[0], b_addr[0][ks] + so);
            ldsm4(bh[1], b_addr[1][ks] + so);
            ldsm4(bh[2], b_addr[2][ks] + so);
            ldsm4(bh[3], b_addr[3][ks] + so);
            ldsm4(ah[1], a_addr[1][ks] + so);

            // hh chain, mf = 0  (al ldsm hides beneath)
#pragma unroll
            for (int nf = 0; nf < 8; ++nf)
                mma_bf16(acc[0][nf], ah[0],
                         bh[nf >> 1][(nf & 1) * 2], bh[nf >> 1][(nf & 1) * 2 + 1]);
            ldsm4(al[0], a_addr[0][ks] + so + (A_LO_OFF - A_HI_OFF));
            ldsm4(al[1], a_addr[1][ks] + so + (A_LO_OFF - A_HI_OFF));

            // hh chain, mf = 1  (bl ldsm hides beneath)
#pragma unroll
            for (int nf = 0; nf < 8; ++nf)
                mma_bf16(acc[1][nf], ah[1],
                         bh[nf >> 1][(nf & 1) * 2], bh[nf >> 1][(nf & 1) * 2 + 1]);
            ldsm4(bl[0], b_addr[0][ks] + so + (B_LO_OFF - B_HI_OFF));
            ldsm4(bl[1], b_addr[1][ks] + so + (B_LO_OFF - B_HI_OFF));
            ldsm4(bl[2], b_addr[2][ks] + so + (B_LO_OFF - B_HI_OFF));
            ldsm4(bl[3], b_addr[3][ks] + so + (B_LO_OFF - B_HI_OFF));

            // refill part 1 (A): after ALL ldsm of this stage (ks==1 only)
            if (ks == 1 && pre)
                load_warp_A(wbase + so, i0r, knext, lane);

            // hl chain
#pragma unroll
            for (int mf = 0; mf < 2; ++mf)
#pragma unroll
                for (int nf = 0; nf < 8; ++nf)
                    mma_bf16(acc[mf][nf], ah[mf],
                             bl[nf >> 1][(nf & 1) * 2], bl[nf >> 1][(nf & 1) * 2 + 1]);

            // refill part 2 (B) + single commit per iteration
            if (ks == 1) {
                if (pre) load_warp_B(wbase + so, j0, knext, lane);
                cp_commit();
            }

            // lh chain
#pragma unroll
            for (int mf = 0; mf < 2; ++mf)
#pragma unroll
                for (int nf = 0; nf < 8; ++nf)
                    mma_bf16(acc[mf][nf], al[mf],
                             bh[nf >> 1][(nf & 1) * 2], bh[nf >> 1][(nf & 1) * 2 + 1]);
        }
    }

    // ---- epilogue: 4-set reduction + write (tile, mirror, diag) ----
    __syncthreads();                          // all warps done with private bufs
    const int r0   = lane >> 2;
    const int cpos = (lane & 3) * 2;
    const bool diagTile = (ti == tj);
    float (*sdiag)[64] = (float (*)[64])(smem + SDIAG_OFF);

    if (diagTile) {                           // per-column sums of E_cos_sq
        const int c  = tid & 63;
        const int gq = tid >> 6;              // 0..3
        float s = 0.0f;
#pragma unroll 8
        for (int p = gq * 64; p < gq * 64 + 64; ++p)
            s += g_dpart[p * KQ + j0 + c];
        sdiag[gq][c] = s;
    }

    if (kset >= 1) {
        float (*red)[RED_STRIDE] =
            (float (*)[RED_STRIDE])(smem + (size_t)(kset - 1) * RED_BYTES);
#pragma unroll
        for (int mf = 0; mf < 2; ++mf)
#pragma unroll
            for (int nf = 0; nf < 8; ++nf) {
                const int rl = wm + mf * 16 + r0;
                const int cl = nf * 8 + cpos;
                red[rl][cl]         = acc[mf][nf][0];
                red[rl][cl + 1]     = acc[mf][nf][1];
                red[rl + 8][cl]     = acc[mf][nf][2];
                red[rl + 8][cl + 1] = acc[mf][nf][3];
            }
    }
    __syncthreads();

    if (kset == 0) {
        float* __restrict__ G = out + EPHI_SZ;
        float (*red0)[RED_STRIDE] = (float (*)[RED_STRIDE])(smem);
        float (*red1)[RED_STRIDE] = (float (*)[RED_STRIDE])(smem + RED_BYTES);
        float (*red2)[RED_STRIDE] = (float (*)[RED_STRIDE])(smem + 2 * RED_BYTES);
#pragma unroll
        for (int mf = 0; mf < 2; ++mf)
#pragma unroll
            for (int nf = 0; nf < 8; ++nf)
#pragma unroll
                for (int r2 = 0; r2 < 4; ++r2) {
                    const int rl = wm + mf * 16 + r0 + (r2 >> 1) * 8;
                    const int cl = nf * 8 + cpos + (r2 & 1);
                    const int gi = i0 + rl;
                    const int gj = j0 + cl;
                    float val = acc[mf][nf][r2]
                              + red0[rl][cl] + red1[rl][cl] + red2[rl][cl];
                    if (diagTile && gi == gj)
                        val = sdiag[0][cl] + sdiag[1][cl]
                            + sdiag[2][cl] + sdiag[3][cl];
                    G[(size_t)gi * KQ + gj] = val;
                    G[(size_t)gj * KQ + gi] = val;
                }
    }
}

// ---------------------------------------------------------------------------
extern "C" void kernel_launch(void* const* d_in, const int* in_sizes, int n_in,
                              void* d_out, int out_size)
{
    const float* X           = (const float*)d_in[0];
    const float* z           = (const float*)d_in[1];
    const float* weight      = (const float*)d_in[2];
    const float* mu          = (const float*)d_in[3];
    const float* stdv        = (const float*)d_in[4];
    const float* alpha       = (const float*)d_in[5];
    const float* var_mu_w    = (const float*)d_in[6];
    const float* var_sigma_w = (const float*)d_in[7];
    float* out = (float*)d_out;

    cudaFuncSetAttribute(syrk_mma_kernel,
                         cudaFuncAttributeMaxDynamicSharedMemorySize, SMEM_SYRK);

    dim3 egrid(KQ / 256, N_PTS / 32);
    ephi_kernel<<<egrid, 256>>>(X, z, weight, mu, stdv, alpha,
                                var_mu_w, var_sigma_w, out);

    syrk_mma_kernel<<<136, 256, SMEM_SYRK>>>(out);
}

// round 12
// speedup vs baseline: 1.0531x; 1.0331x over previous
#include <cuda_runtime.h>
#include <cuda_bf16.h>
#include <math.h>
#include <stdint.h>

#define N_PTS   8192
#define D_DIM   8
#define K_DIM   64
#define Q_DIM   16
#define KQ      1024
#define TWO_PI  6.283185307179586f

#define EPHI_SZ (N_PTS * KQ)    // 8388608
#define G_SZ    (KQ * KQ)       // 1048576
// d_out layout: [E_phi (N,KQ) | G (KQ,KQ) | E_cos_sq (N,KQ)]

// -------- device scratch --------
__device__ float g_dpart[256 * KQ];
__device__ __nv_bfloat16 g_hi[(size_t)KQ * N_PTS];
__device__ __nv_bfloat16 g_lo[(size_t)KQ * N_PTS];

// ---------------------------------------------------------------------------
// helpers
// ---------------------------------------------------------------------------
__device__ __forceinline__ uint32_t smem_u32(const void* p) {
    uint32_t a;
    asm("{ .reg .u64 t; cvta.to.shared.u64 t, %1; cvt.u32.u64 %0, t; }"
        : "=r"(a) : "l"(p));
    return a;
}
__device__ __forceinline__ void cp16(uint32_t dst, const void* src) {
    asm volatile("cp.async.cg.shared.global [%0], [%1], 16;"
                 :: "r"(dst), "l"(src));
}
__device__ __forceinline__ void cp_commit() {
    asm volatile("cp.async.commit_group;" ::: "memory");
}
template <int N>
__device__ __forceinline__ void cp_wait() {
    asm volatile("cp.async.wait_group %0;" :: "n"(N) : "memory");
}
__device__ __forceinline__ void ldsm4(uint32_t* r, uint32_t addr) {
    asm volatile("ldmatrix.sync.aligned.m8n8.x4.shared.b16 {%0,%1,%2,%3}, [%4];"
                 : "=r"(r[0]), "=r"(r[1]), "=r"(r[2]), "=r"(r[3]) : "r"(addr));
}
__device__ __forceinline__ void mma_bf16(float* c, const uint32_t* a,
                                         uint32_t b0, uint32_t b1) {
    asm volatile(
        "mma.sync.aligned.m16n8k16.row.col.f32.bf16.bf16.f32 "
        "{%0,%1,%2,%3}, {%4,%5,%6,%7}, {%8,%9}, {%0,%1,%2,%3};"
        : "+f"(c[0]), "+f"(c[1]), "+f"(c[2]), "+f"(c[3])
        : "r"(a[0]), "r"(a[1]), "r"(a[2]), "r"(a[3]), "r"(b0), "r"(b1));
}

// swizzled offset within a 64B-row warp-private buffer (16B granules)
__device__ __forceinline__ uint32_t swz(int row, int seg) {
    return (uint32_t)(row * 64 + ((seg ^ ((row >> 1) & 3)) << 4));
}

// ---------------------------------------------------------------------------
// Kernel 1: fused E_phi, E_cos_sq, split-bf16 transposed hi/lo, diag partials.
// Coefficient tables computed per-block in smem.
// ---------------------------------------------------------------------------
__global__ void __launch_bounds__(256) ephi_kernel(const float* __restrict__ X,
                            const float* __restrict__ z,
                            const float* __restrict__ weight,
                            const float* __restrict__ mu,
                            const float* __restrict__ stdv,
                            const float* __restrict__ alpha,
                            const float* __restrict__ var_mu_w,
                            const float* __restrict__ var_sigma_w,
                            float* __restrict__ out)
{
    const int tid = threadIdx.x;
    const int kq0 = blockIdx.x * 256;
    const int kq  = kq0 + tid;
    const int n0  = blockIdx.y * 32;

    __shared__ float Xs[256];
    __shared__ float s_mp[128], s_sp[128];     // mean_p, std_p per (d,q)
    __shared__ __nv_bfloat16 s_hi[256][34];
    __shared__ __nv_bfloat16 s_lo[256][34];

    Xs[tid] = TWO_PI * X[n0 * D_DIM + tid];
    if (tid < 128) {
        s_mp[tid] = 1.0f / (mu[tid] + 1e-8f);
        s_sp[tid] = 1.0f / (TWO_PI * stdv[tid] + 1e-8f);
    }
    __syncthreads();

    const int q = kq & (Q_DIM - 1);
    float ew[D_DIM], cc[D_DIM], zz[D_DIM];
#pragma unroll
    for (int d = 0; d < D_DIM; ++d) {
        const float mp = s_mp[d * Q_DIM + q];
        const float sp = s_sp[d * Q_DIM + q];
        ew[d] = mp + sp * var_mu_w[d * KQ + kq];
        cc[d] = sp * sp * var_sigma_w[d * KQ + kq];
        zz[d] = TWO_PI * z[d * KQ + kq];
    }
    const float a    = alpha[kq];
    const float coef = 2.0f * weight[q] * (1.0f / (float)K_DIM);
    const float sq   = sqrtf(coef);

    float* __restrict__ outE = out;
    float* __restrict__ outC = out + EPHI_SZ + G_SZ;

    float dsum = 0.0f;
#pragma unroll 4
    for (int r = 0; r < 32; ++r) {
        float phase = 0.0f, s = 0.0f;
#pragma unroll
        for (int d = 0; d < D_DIM; ++d) {
            float xb = Xs[r * D_DIM + d] - zz[d];
            phase = fmaf(xb, ew[d], phase);
            s     = fmaf(cc[d], xb * xb, s);
        }
        float cw    = __cosf(a + phase);
        float decay = __expf(-0.5f * s);

        const int n = n0 + r;
        float E = sq * decay * cw;
        outE[n * KQ + kq] = E;

        float d2  = decay * decay;
        float d4  = d2 * d2;
        float c2w = 2.0f * cw * cw - 1.0f;
        float ecs = coef * (0.5f + 0.5f * d4 * c2w);
        outC[n * KQ + kq] = ecs;
        dsum += ecs;

        __nv_bfloat16 h = __float2bfloat16(E);
        s_hi[tid][r] = h;
        s_lo[tid][r] = __float2bfloat16(E - __bfloat162float(h));
    }
    g_dpart[blockIdx.y * KQ + kq] = dsum;
    __syncthreads();

    uint32_t* __restrict__ H = (uint32_t*)g_hi;
    uint32_t* __restrict__ L = (uint32_t*)g_lo;
#pragma unroll
    for (int i = 0; i < 16; ++i) {
        int v   = tid + i * 256;
        int row = v >> 4;
        int seg = v & 15;
        uint32_t h2 = *(const uint32_t*)&s_hi[row][seg * 2];
        uint32_t l2 = *(const uint32_t*)&s_lo[row][seg * 2];
        size_t o = ((size_t)(kq0 + row) * N_PTS + n0) / 2 + seg;
        H[o] = h2;
        L[o] = l2;
    }
}

// ---------------------------------------------------------------------------
// Kernel 2: SYRK, warp-autonomous pipelines (NO mainloop __syncthreads).
// EXACT R8 mainloop (proven 71us / tensor 63%): batched 12-ldsm head,
// hh/hl/lh chains, refill after all stage ldsm (ks==1), single commit/iter,
// cp_wait<1>. Epilogue: 4-set smem reduce + write/mirror; diagonal tiles
// reduce g_dpart in-place (proven in R10/R11).
// ---------------------------------------------------------------------------
#define A_HI_OFF 0
#define A_LO_OFF 2048
#define B_HI_OFF 4096
#define B_LO_OFF 8192
#define WSTAGE   12288
#define WBUF     (2 * WSTAGE)        // 24576 per warp
#define SMEM_SYRK (8 * WBUF)         // 196608
#define NSC 64
#define RED_STRIDE 65
#define RED_BYTES (64 * RED_STRIDE * 4)   // 16640
#define SDIAG_OFF (3 * RED_BYTES)         // 49920

__device__ __forceinline__ void load_warp(uint32_t stage_base, int i0r, int j0,
                                          size_t koff, int lane)
{
    // A: 32 rows x 32k, hi+lo = 256 16B-chunks; B: 64 rows x 32k = 512 chunks
#pragma unroll
    for (int it = 0; it < 8; ++it) {
        int cid = it * 32 + lane;
        int h   = cid >> 7;
        int rc  = cid & 127;
        int row = rc >> 2;
        int seg = rc & 3;
        uint32_t dst = stage_base + (uint32_t)(h ? A_LO_OFF : A_HI_OFF) + swz(row, seg);
        const __nv_bfloat16* base = h ? g_lo : g_hi;
        cp16(dst, (const char*)(base + (size_t)(i0r + row) * N_PTS + koff) + seg * 16);
    }
#pragma unroll
    for (int it = 0; it < 16; ++it) {
        int cid = it * 32 + lane;
        int h   = cid >> 8;
        int rc  = cid & 255;
        int row = rc >> 2;
        int seg = rc & 3;
        uint32_t dst = stage_base + (uint32_t)(h ? B_LO_OFF : B_HI_OFF) + swz(row, seg);
        const __nv_bfloat16* base = h ? g_lo : g_hi;
        cp16(dst, (const char*)(base + (size_t)(j0 + row) * N_PTS + koff) + seg * 16);
    }
}

__global__ void __launch_bounds__(256, 1) syrk_mma_kernel(float* __restrict__ out)
{
    extern __shared__ __align__(1024) char smem[];
    const uint32_t sbase = smem_u32(smem);
    const int tid  = threadIdx.x;
    const int lane = tid & 31;
    const int wid  = tid >> 5;
    const int ms   = wid & 1;               // m-half
    const int kset = wid >> 1;              // k-quarter
    const int wm   = ms * 32;
    const uint32_t wbase = sbase + (uint32_t)wid * WBUF;

    int b = blockIdx.x, ti = 0, rem = b;
    while (rem >= 16 - ti) { rem -= 16 - ti; ++ti; }
    const int tj = ti + rem;
    const int i0 = ti * 64;
    const int j0 = tj * 64;
    const int i0r = i0 + wm;

    // ldmatrix addresses within the private buffer
    const int g  = lane >> 3;
    const int rr = lane & 7;
    uint32_t a_addr[2][2], b_addr[4][2];
#pragma unroll
    for (int mf = 0; mf < 2; ++mf)
#pragma unroll
        for (int ks = 0; ks < 2; ++ks) {
            int m   = mf * 16 + rr + (g & 1) * 8;
            int seg = (g >> 1) + ks * 2;
            a_addr[mf][ks] = wbase + A_HI_OFF + swz(m, seg);
        }
#pragma unroll
    for (int nf2 = 0; nf2 < 4; ++nf2)
#pragma unroll
        for (int ks = 0; ks < 2; ++ks) {
            int n   = nf2 * 16 + rr + (g >> 1) * 8;
            int seg = (g & 1) + ks * 2;
            b_addr[nf2][ks] = wbase + B_HI_OFF + swz(n, seg);
        }

    float acc[2][8][4];
#pragma unroll
    for (int mf = 0; mf < 2; ++mf)
#pragma unroll
        for (int nf = 0; nf < 8; ++nf)
#pragma unroll
            for (int r2 = 0; r2 < 4; ++r2) acc[mf][nf][r2] = 0.0f;

    const size_t kbase = (size_t)kset * 32;
    load_warp(wbase,          i0r, j0, kbase,       lane); cp_commit();
    load_warp(wbase + WSTAGE, i0r, j0, kbase + 128, lane); cp_commit();

    for (int sc = 0; sc < NSC; ++sc) {
        cp_wait<1>();                         // this warp's chunk sc complete
        const uint32_t so = (uint32_t)(sc & 1) * WSTAGE;

#pragma unroll
        for (int ks = 0; ks < 2; ++ks) {
            uint32_t ah[2][4], al[2][4], bh[4][4], bl[4][4];
            ldsm4(ah[0], a_addr[0][ks] + so);
            ldsm4(ah[1], a_addr[1][ks] + so);
            ldsm4(al[0], a_addr[0][ks] + so + (A_LO_OFF - A_HI_OFF));
            ldsm4(al[1], a_addr[1][ks] + so + (A_LO_OFF - A_HI_OFF));
#pragma unroll
            for (int nf2 = 0; nf2 < 4; ++nf2) {
                ldsm4(bh[nf2], b_addr[nf2][ks] + so);
                ldsm4(bl[nf2], b_addr[nf2][ks] + so + (B_LO_OFF - B_HI_OFF));
            }

            // hh chain
#pragma unroll
            for (int mf = 0; mf < 2; ++mf)
#pragma unroll
                for (int nf = 0; nf < 8; ++nf)
                    mma_bf16(acc[mf][nf], ah[mf],
                             bh[nf >> 1][(nf & 1) * 2], bh[nf >> 1][(nf & 1) * 2 + 1]);

            // refill: after ALL ldsm of this stage (ks==1 only), single commit
            if (ks == 1) {
                if (sc + 2 < NSC)
                    load_warp(wbase + so, i0r, j0,
                              kbase + (size_t)(sc + 2) * 128, lane);
                cp_commit();
            }

            // hl chain
#pragma unroll
            for (int mf = 0; mf < 2; ++mf)
#pragma unroll
                for (int nf = 0; nf < 8; ++nf)
                    mma_bf16(acc[mf][nf], ah[mf],
                             bl[nf >> 1][(nf & 1) * 2], bl[nf >> 1][(nf & 1) * 2 + 1]);
            // lh chain
#pragma unroll
            for (int mf = 0; mf < 2; ++mf)
#pragma unroll
                for (int nf = 0; nf < 8; ++nf)
                    mma_bf16(acc[mf][nf], al[mf],
                             bh[nf >> 1][(nf & 1) * 2], bh[nf >> 1][(nf & 1) * 2 + 1]);
        }
    }

    // ---- epilogue: 4-set reduction + write (tile, mirror, diag) ----
    __syncthreads();                          // all warps done with private bufs
    const int r0   = lane >> 2;
    const int cpos = (lane & 3) * 2;
    const bool diagTile = (ti == tj);
    float (*sdiag)[64] = (float (*)[64])(smem + SDIAG_OFF);

    if (diagTile) {                           // per-column sums of E_cos_sq
        const int c  = tid & 63;
        const int gq = tid >> 6;              // 0..3
        float s = 0.0f;
#pragma unroll 8
        for (int p = gq * 64; p < gq * 64 + 64; ++p)
            s += g_dpart[p * KQ + j0 + c];
        sdiag[gq][c] = s;
    }

    if (kset >= 1) {
        float (*red)[RED_STRIDE] =
            (float (*)[RED_STRIDE])(smem + (size_t)(kset - 1) * RED_BYTES);
#pragma unroll
        for (int mf = 0; mf < 2; ++mf)
#pragma unroll
            for (int nf = 0; nf < 8; ++nf) {
                const int rl = wm + mf * 16 + r0;
                const int cl = nf * 8 + cpos;
                red[rl][cl]         = acc[mf][nf][0];
                red[rl][cl + 1]     = acc[mf][nf][1];
                red[rl + 8][cl]     = acc[mf][nf][2];
                red[rl + 8][cl + 1] = acc[mf][nf][3];
            }
    }
    __syncthreads();

    if (kset == 0) {
        float* __restrict__ G = out + EPHI_SZ;
        float (*red0)[RED_STRIDE] = (float (*)[RED_STRIDE])(smem);
        float (*red1)[RED_STRIDE] = (float (*)[RED_STRIDE])(smem + RED_BYTES);
        float (*red2)[RED_STRIDE] = (float (*)[RED_STRIDE])(smem + 2 * RED_BYTES);
#pragma unroll
        for (int mf = 0; mf < 2; ++mf)
#pragma unroll
            for (int nf = 0; nf < 8; ++nf)
#pragma unroll
                for (int r2 = 0; r2 < 4; ++r2) {
                    const int rl = wm + mf * 16 + r0 + (r2 >> 1) * 8;
                    const int cl = nf * 8 + cpos + (r2 & 1);
                    const int gi = i0 + rl;
                    const int gj = j0 + cl;
                    float val = acc[mf][nf][r2]
                              + red0[rl][cl] + red1[rl][cl] + red2[rl][cl];
                    if (diagTile && gi == gj)
                        val = sdiag[0][cl] + sdiag[1][cl]
                            + sdiag[2][cl] + sdiag[3][cl];
                    G[(size_t)gi * KQ + gj] = val;
                    G[(size_t)gj * KQ + gi] = val;
                }
    }
}

// ---------------------------------------------------------------------------
extern "C" void kernel_launch(void* const* d_in, const int* in_sizes, int n_in,
                              void* d_out, int out_size)
{
    const float* X           = (const float*)d_in[0];
    const float* z           = (const float*)d_in[1];
    const float* weight      = (const float*)d_in[2];
    const float* mu          = (const float*)d_in[3];
    const float* stdv        = (const float*)d_in[4];
    const float* alpha       = (const float*)d_in[5];
    const float* var_mu_w    = (const float*)d_in[6];
    const float* var_sigma_w = (const float*)d_in[7];
    float* out = (float*)d_out;

    cudaFuncSetAttribute(syrk_mma_kernel,
                         cudaFuncAttributeMaxDynamicSharedMemorySize, SMEM_SYRK);

    dim3 egrid(KQ / 256, N_PTS / 32);
    ephi_kernel<<<egrid, 256>>>(X, z, weight, mu, stdv, alpha,
                                var_mu_w, var_sigma_w, out);

    syrk_mma_kernel<<<136, 256, SMEM_SYRK>>>(out);
}